// round 10
// baseline (speedup 1.0000x reference)
#include <cuda_runtime.h>
#include <cuda_fp16.h>
#include <cstdint>

// ---------------- problem constants ----------------
#define HID 768
#define W1ROWS 1536
#define MAXK 64
#define NMENT 4096

// ---------------- tiling ----------------
#define BM 128
#define BN 128
#define BK 32                          // 32 k-halves per tile (2 mma k16 steps)
#define NKT (HID / BK)                 // 24 = 8 * NSTAGE
#define NTHREADS 256
#define SROWH 40                       // smem row stride in halves; 20r mod 32 permutes banks
#define A_STAGE_BYTES (BM * SROWH * 2) // 10240
#define B_STAGE_BYTES (BN * SROWH * 2) // 10240
#define STAGE_BYTES (A_STAGE_BYTES + B_STAGE_BYTES)   // 20480
#define NSTAGE 3
#define SMEM_BYTES (NSTAGE * STAGE_BYTES)             // 61440 -> 2 CTAs/SM

// ---------------- device scratch (static, no allocs) ----------------
__device__ float  g_Mpart[NMENT * HID];     // mention @ W1_top + b1 (fp32)
__device__ __half g_W1TH[HID * W1ROWS];     // W1 transposed -> [n][k] fp16

// ---------------- helpers ----------------
__device__ __forceinline__ void cp_async16(void* sptr, const void* gptr) {
    uint32_t s = (uint32_t)__cvta_generic_to_shared(sptr);
    asm volatile("cp.async.cg.shared.global [%0], [%1], 16;\n" :: "r"(s), "l"(gptr));
}
__device__ __forceinline__ void cp_commit() { asm volatile("cp.async.commit_group;\n"); }
template <int W_>
__device__ __forceinline__ void cp_wait() { asm volatile("cp.async.wait_group %0;\n" :: "n"(W_)); }

__device__ __forceinline__ void mma_f16(float& c0, float& c1, float& c2, float& c3,
                                        uint32_t a0, uint32_t a1, uint32_t a2, uint32_t a3,
                                        uint32_t b0, uint32_t b1) {
    asm volatile(
        "mma.sync.aligned.m16n8k16.row.col.f32.f16.f16.f32 "
        "{%0,%1,%2,%3}, {%4,%5,%6,%7}, {%8,%9}, {%0,%1,%2,%3};\n"
        : "+f"(c0), "+f"(c1), "+f"(c2), "+f"(c3)
        : "r"(a0), "r"(a1), "r"(a2), "r"(a3), "r"(b0), "r"(b1));
}

__device__ __forceinline__ uint32_t f2h2(float x, float y) {
    __half2 h = __floats2half2_rn(x, y);
    return *reinterpret_cast<uint32_t*>(&h);
}

// ---------------- aux kernels ----------------
__global__ void init_out_kernel(float* __restrict__ out, const float* __restrict__ prior,
                                const float* __restrict__ nota, int n) {
    int i = blockIdx.x * blockDim.x + threadIdx.x;
    if (i < n * (MAXK + 1)) {
        int k = i % (MAXK + 1);
        int row = i / (MAXK + 1);
        out[i] = (k < MAXK) ? 0.5f * prior[row * MAXK + k] : nota[0];
    }
}

// g_W1TH[n][k] = fp16(W1[k][n]);  W1: [1536, 768] row-major
__global__ void transpose_kernel(const float* __restrict__ W1) {
    __shared__ float t[32][33];
    int n0 = blockIdx.x * 32, k0 = blockIdx.y * 32;
    int tx = threadIdx.x, ty = threadIdx.y;
#pragma unroll
    for (int i = 0; i < 4; ++i)
        t[ty + 8 * i][tx] = W1[(size_t)(k0 + ty + 8 * i) * HID + n0 + tx];
    __syncthreads();
#pragma unroll
    for (int i = 0; i < 4; ++i)
        g_W1TH[(size_t)(n0 + ty + 8 * i) * W1ROWS + k0 + tx] = __float2half_rn(t[tx][ty + 8 * i]);
}

// ---------------- fp16-MMA GEMM, fp16 A smem, 2 CTAs/SM ----------------
// A fp32 global -> in-kernel fp16 smem (LDG+CVT+STS, one-row-per-lane mapping);
// B fp16 via cp.async. Fragments via direct LDS.32 (conflict-free at stride 40h).
// MAIN=false: g_Mpart = A @ W1T[:, kOff..]^T + b1
// MAIN=true : fused cand GEMM + Mpart gather + relu + W2 dot + scatter atomicAdd
template <bool MAIN>
__global__ __launch_bounds__(NTHREADS, 2)
void gemm_kernel(const float* __restrict__ A, int kOff,
                 const float* __restrict__ b1, const float* __restrict__ W2,
                 const float* __restrict__ b2v,
                 const int* __restrict__ midx, const int* __restrict__ cidx,
                 float* __restrict__ out) {
    extern __shared__ char smem[];

    const int tid   = threadIdx.x;
    const int warp  = tid >> 5;
    const int lane  = tid & 31;
    const int warpM = warp >> 2;          // 0..1  (64 rows)
    const int warpN = warp & 3;           // 0..3  (32 cols)
    const int gid   = lane >> 2;          // 0..7
    const int tg    = lane & 3;           // 0..3

    // A loader: one row per lane (conflict-free STS.128 at stride 40 halves)
    const int rL = tid & 127;             // row
    const int cL = (tid >> 7) << 4;       // 0 or 16 (half-chunk within 32-k row)

    const float*  Ablk = A + (size_t)blockIdx.y * BM * HID;
    const __half* Bblk = g_W1TH + (size_t)blockIdx.x * BN * W1ROWS + kOff;

    float c[4][4][4];
#pragma unroll
    for (int mi = 0; mi < 4; ++mi)
#pragma unroll
        for (int ni = 0; ni < 4; ++ni)
#pragma unroll
            for (int j = 0; j < 4; ++j) c[mi][ni][j] = 0.f;

    auto ldgA = [&](int kt, float4* f) {
        const float* p = Ablk + (size_t)rL * HID + kt * BK + cL;
#pragma unroll
        for (int i = 0; i < 4; ++i) f[i] = *reinterpret_cast<const float4*>(p + 4 * i);
    };
    auto stsA = [&](int stage, const float4* f) {
        uint32_t h[8];
#pragma unroll
        for (int i = 0; i < 4; ++i) {
            h[2 * i]     = f2h2(f[i].x, f[i].y);
            h[2 * i + 1] = f2h2(f[i].z, f[i].w);
        }
        char* dst = smem + stage * STAGE_BYTES + (rL * SROWH + cL) * 2;
        *reinterpret_cast<uint4*>(dst)      = make_uint4(h[0], h[1], h[2], h[3]);
        *reinterpret_cast<uint4*>(dst + 16) = make_uint4(h[4], h[5], h[6], h[7]);
    };
    auto loadB = [&](int kt, int stage) {
        char* sb = smem + stage * STAGE_BYTES + A_STAGE_BYTES;
#pragma unroll
        for (int i = 0; i < 2; ++i) {                 // B: 128 rows x 4 x 16B
            int idx = tid + i * NTHREADS;
            int n = idx >> 2, cc = idx & 3;
            cp_async16(sb + (n * SROWH + cc * 8) * 2,
                       Bblk + (size_t)n * W1ROWS + kt * BK + cc * 8);
        }
    };

    // compute one k-tile from compile-time stage (direct LDS.32 fp16 fragments)
    auto compute_tile = [&](int stage) {
        const __half2* sa2 = reinterpret_cast<const __half2*>(smem + stage * STAGE_BYTES);
        const __half2* sb2 = reinterpret_cast<const __half2*>(smem + stage * STAGE_BYTES + A_STAGE_BYTES);
        const int S2 = SROWH / 2;   // 20 half2 per row
#pragma unroll
        for (int ks = 0; ks < 2; ++ks) {
            const int kh = ks * 8;                    // half2 column offset
            uint32_t b[4][2];
#pragma unroll
            for (int ni = 0; ni < 4; ++ni) {
                const int col = warpN * 32 + ni * 8 + gid;
                b[ni][0] = *reinterpret_cast<const uint32_t*>(&sb2[col * S2 + kh + tg]);
                b[ni][1] = *reinterpret_cast<const uint32_t*>(&sb2[col * S2 + kh + tg + 4]);
            }
#pragma unroll
            for (int mi = 0; mi < 4; ++mi) {
                const int r = warpM * 64 + mi * 16 + gid;
                uint32_t a0 = *reinterpret_cast<const uint32_t*>(&sa2[r * S2 + kh + tg]);
                uint32_t a1 = *reinterpret_cast<const uint32_t*>(&sa2[(r + 8) * S2 + kh + tg]);
                uint32_t a2 = *reinterpret_cast<const uint32_t*>(&sa2[r * S2 + kh + tg + 4]);
                uint32_t a3 = *reinterpret_cast<const uint32_t*>(&sa2[(r + 8) * S2 + kh + tg + 4]);
#pragma unroll
                for (int ni = 0; ni < 4; ++ni)
                    mma_f16(c[mi][ni][0], c[mi][ni][1], c[mi][ni][2], c[mi][ni][3],
                            a0, a1, a2, a3, b[ni][0], b[ni][1]);
            }
        }
    };

    // prolog: stages 0,1
    {
        float4 f[4];
        ldgA(0, f); stsA(0, f);
        ldgA(1, f); stsA(1, f);
    }
    loadB(0, 0); cp_commit();
    loadB(1, 1); cp_commit();

    float4 fbuf[4];
    for (int kb = 0; kb < NKT / NSTAGE; ++kb) {
#pragma unroll
        for (int s = 0; s < NSTAGE; ++s) {
            const int kt = kb * NSTAGE + s;
            if (kt < NKT - 1) cp_wait<1>(); else cp_wait<0>();
            __syncthreads();
            if (kt + 2 < NKT) {
                ldgA(kt + 2, fbuf);                  // global fetch early (long latency)
                loadB(kt + 2, (s + 2) % NSTAGE);     // compile-time stage
                cp_commit();
            }
            compute_tile(s);
            if (kt + 2 < NKT) stsA((s + 2) % NSTAGE, fbuf);  // stage free: last read at kt-1
        }
    }

    const int rowBase = blockIdx.y * BM + warpM * 64;
    const int colBase = blockIdx.x * BN + warpN * 32;

    if (MAIN) {
        float w2v[4][2];
#pragma unroll
        for (int ni = 0; ni < 4; ++ni) {
            w2v[ni][0] = __ldg(W2 + colBase + ni * 8 + tg * 2);
            w2v[ni][1] = __ldg(W2 + colBase + ni * 8 + tg * 2 + 1);
        }
#pragma unroll
        for (int mi = 0; mi < 4; ++mi)
#pragma unroll
            for (int rr = 0; rr < 2; ++rr) {
                const int prow = rowBase + mi * 16 + rr * 8 + gid;
                const int m = __ldg(midx + prow);
                const float* mp = g_Mpart + (size_t)m * HID;
                float acc = 0.f;
#pragma unroll
                for (int ni = 0; ni < 4; ++ni) {
                    const int col = colBase + ni * 8 + tg * 2;
                    float v0 = c[mi][ni][rr * 2]     + __ldg(mp + col);
                    float v1 = c[mi][ni][rr * 2 + 1] + __ldg(mp + col + 1);
                    acc = fmaf(fmaxf(v0, 0.f), w2v[ni][0], acc);
                    acc = fmaf(fmaxf(v1, 0.f), w2v[ni][1], acc);
                }
                acc += __shfl_xor_sync(0xffffffffu, acc, 1);
                acc += __shfl_xor_sync(0xffffffffu, acc, 2);
                if (tg == 0) {
                    if (blockIdx.x == 0 && warpN == 0) acc += __ldg(b2v);
                    atomicAdd(out + (size_t)m * (MAXK + 1) + __ldg(cidx + prow), acc);
                }
            }
    } else {
#pragma unroll
        for (int mi = 0; mi < 4; ++mi)
#pragma unroll
            for (int rr = 0; rr < 2; ++rr) {
                const int row = rowBase + mi * 16 + rr * 8 + gid;
#pragma unroll
                for (int ni = 0; ni < 4; ++ni) {
                    const int col = colBase + ni * 8 + tg * 2;
                    float2 v;
                    v.x = c[mi][ni][rr * 2]     + __ldg(b1 + col);
                    v.y = c[mi][ni][rr * 2 + 1] + __ldg(b1 + col + 1);
                    *reinterpret_cast<float2*>(&g_Mpart[(size_t)row * HID + col]) = v;
                }
            }
    }
}

// ---------------- launch ----------------
extern "C" void kernel_launch(void* const* d_in, const int* in_sizes, int n_in,
                              void* d_out, int out_size) {
    const float* mention = (const float*)d_in[0];  // [4096, 768]
    const float* cand    = (const float*)d_in[1];  // [131072, 768]
    const float* W1      = (const float*)d_in[2];  // [1536, 768]
    const float* b1      = (const float*)d_in[3];  // [768]
    const float* W2      = (const float*)d_in[4];  // [768, 1]
    const float* b2      = (const float*)d_in[5];  // [1]
    const float* prior   = (const float*)d_in[6];  // [4096, 64]
    const float* nota    = (const float*)d_in[7];  // []
    const int*   midx    = (const int*)d_in[8];    // [T]
    const int*   cidx    = (const int*)d_in[9];    // [T]
    float* out = (float*)d_out;                    // [4096, 65]

    const int N = in_sizes[0] / HID;   // 4096
    const int T = in_sizes[1] / HID;   // 131072

    cudaFuncSetAttribute(gemm_kernel<false>, cudaFuncAttributeMaxDynamicSharedMemorySize, SMEM_BYTES);
    cudaFuncSetAttribute(gemm_kernel<true>,  cudaFuncAttributeMaxDynamicSharedMemorySize, SMEM_BYTES);

    // 0) out = 0.5*prior (+ nota col)
    init_out_kernel<<<(N * (MAXK + 1) + 255) / 256, 256>>>(out, prior, nota, N);

    // 1) W1T (fp16) = W1^T
    transpose_kernel<<<dim3(HID / 32, W1ROWS / 32), dim3(32, 8)>>>(W1);

    // 2) Mpart = mention @ W1_top + b1
    gemm_kernel<false><<<dim3(HID / BN, N / BM), NTHREADS, SMEM_BYTES>>>(
        mention, 0, b1, W2, b2, nullptr, nullptr, out);

    // 3) fused: cand @ W1_bot -> +Mpart -> relu -> @W2 (+b2) -> scatter-add
    gemm_kernel<true><<<dim3(HID / BN, T / BM), NTHREADS, SMEM_BYTES>>>(
        cand, HID, b1, W2, b2, midx, cidx, out);
}

// round 11
// speedup vs baseline: 1.4983x; 1.4983x over previous
#include <cuda_runtime.h>
#include <cuda_fp16.h>
#include <cstdint>

// ---------------- problem constants ----------------
#define HID 768
#define W1ROWS 1536
#define MAXK 64
#define NMENT 4096
#define TPAIR 131072

// ---------------- tiling ----------------
#define BM 128
#define BN 128
#define BK 32                          // 32 k-halves per tile (2 mma k16 steps)
#define NKT (HID / BK)                 // 24 = 8 * NSTAGE
#define NTHREADS 256
#define SROWH 40                       // smem row stride in halves (20r mod 32 bank-permutes)
#define A_STAGE_BYTES (BM * SROWH * 2) // 10240
#define B_STAGE_BYTES (BN * SROWH * 2) // 10240
#define STAGE_BYTES (A_STAGE_BYTES + B_STAGE_BYTES)   // 20480
#define NSTAGE 3
#define SMEM_BYTES (NSTAGE * STAGE_BYTES)             // 61440 -> 2 CTAs/SM

// ---------------- device scratch (static, no allocs) ----------------
__device__ float  g_Mpart[NMENT * HID];          // mention @ W1_top + b1 (fp32)
__device__ __half g_W1TH[HID * W1ROWS];          // W1 transposed -> [n][k] fp16
__device__ __half g_candH[(size_t)TPAIR * HID];  // candidate embs fp16
__device__ __half g_mentH[NMENT * HID];          // mention embs fp16

// ---------------- helpers ----------------
__device__ __forceinline__ void cp_async16(void* sptr, const void* gptr) {
    uint32_t s = (uint32_t)__cvta_generic_to_shared(sptr);
    asm volatile("cp.async.cg.shared.global [%0], [%1], 16;\n" :: "r"(s), "l"(gptr));
}
__device__ __forceinline__ void cp_commit() { asm volatile("cp.async.commit_group;\n"); }
template <int W_>
__device__ __forceinline__ void cp_wait() { asm volatile("cp.async.wait_group %0;\n" :: "n"(W_)); }

__device__ __forceinline__ void mma_f16(float& c0, float& c1, float& c2, float& c3,
                                        uint32_t a0, uint32_t a1, uint32_t a2, uint32_t a3,
                                        uint32_t b0, uint32_t b1) {
    asm volatile(
        "mma.sync.aligned.m16n8k16.row.col.f32.f16.f16.f32 "
        "{%0,%1,%2,%3}, {%4,%5,%6,%7}, {%8,%9}, {%0,%1,%2,%3};\n"
        : "+f"(c0), "+f"(c1), "+f"(c2), "+f"(c3)
        : "r"(a0), "r"(a1), "r"(a2), "r"(a3), "r"(b0), "r"(b1));
}

// ---------------- aux kernels ----------------
__global__ void init_out_kernel(float* __restrict__ out, const float* __restrict__ prior,
                                const float* __restrict__ nota, int n) {
    int i = blockIdx.x * blockDim.x + threadIdx.x;
    if (i < n * (MAXK + 1)) {
        int k = i % (MAXK + 1);
        int row = i / (MAXK + 1);
        out[i] = (k < MAXK) ? 0.5f * prior[row * MAXK + k] : nota[0];
    }
}

// fp32 -> fp16 stream convert (4 elems / thread, fully coalesced)
__global__ void convert_kernel(const float* __restrict__ src, __half* __restrict__ dst,
                               long n4) {
    long i = (long)blockIdx.x * blockDim.x + threadIdx.x;
    if (i < n4) {
        float4 v = *reinterpret_cast<const float4*>(src + i * 4);
        __half2 h0 = __floats2half2_rn(v.x, v.y);
        __half2 h1 = __floats2half2_rn(v.z, v.w);
        *reinterpret_cast<uint2*>(dst + i * 4) =
            make_uint2(*reinterpret_cast<uint32_t*>(&h0), *reinterpret_cast<uint32_t*>(&h1));
    }
}

// g_W1TH[n][k] = fp16(W1[k][n]);  W1: [1536, 768] row-major
__global__ void transpose_kernel(const float* __restrict__ W1) {
    __shared__ float t[32][33];
    int n0 = blockIdx.x * 32, k0 = blockIdx.y * 32;
    int tx = threadIdx.x, ty = threadIdx.y;
#pragma unroll
    for (int i = 0; i < 4; ++i)
        t[ty + 8 * i][tx] = W1[(size_t)(k0 + ty + 8 * i) * HID + n0 + tx];
    __syncthreads();
#pragma unroll
    for (int i = 0; i < 4; ++i)
        g_W1TH[(size_t)(n0 + ty + 8 * i) * W1ROWS + k0 + tx] = __float2half_rn(t[tx][ty + 8 * i]);
}

// ---------------- all-fp16 GEMM, cp.async both operands, 2 CTAs/SM ----------------
// MAIN=false: g_Mpart = A @ W1T[:, kOff..]^T + b1
// MAIN=true : fused cand GEMM + Mpart gather + relu + W2 dot + scatter atomicAdd
template <bool MAIN>
__global__ __launch_bounds__(NTHREADS, 2)
void gemm_kernel(const __half* __restrict__ A, int kOff,
                 const float* __restrict__ b1, const float* __restrict__ W2,
                 const float* __restrict__ b2v,
                 const int* __restrict__ midx, const int* __restrict__ cidx,
                 float* __restrict__ out) {
    extern __shared__ char smem[];

    const int tid   = threadIdx.x;
    const int warp  = tid >> 5;
    const int lane  = tid & 31;
    const int warpM = warp >> 2;          // 0..1  (64 rows)
    const int warpN = warp & 3;           // 0..3  (32 cols)
    const int gid   = lane >> 2;          // 0..7
    const int tg    = lane & 3;           // 0..3

    const __half* Ablk = A + (size_t)blockIdx.y * BM * HID;
    const __half* Bblk = g_W1TH + (size_t)blockIdx.x * BN * W1ROWS + kOff;

    float c[4][4][4];
#pragma unroll
    for (int mi = 0; mi < 4; ++mi)
#pragma unroll
        for (int ni = 0; ni < 4; ++ni)
#pragma unroll
            for (int j = 0; j < 4; ++j) c[mi][ni][j] = 0.f;

    auto load_tiles = [&](int kt, int stage) {
        char* sa = smem + stage * STAGE_BYTES;
        char* sb = sa + A_STAGE_BYTES;
        // A: 128 rows x 32 halves (4 x 16B chunks per row) — 8 lanes span 2 rows, coalesced
#pragma unroll
        for (int i = 0; i < 2; ++i) {
            int idx = tid + i * NTHREADS;
            int r = idx >> 2, cc = idx & 3;
            cp_async16(sa + (r * SROWH + cc * 8) * 2, Ablk + (size_t)r * HID + kt * BK + cc * 8);
        }
        // B: 128 rows x 32 halves
#pragma unroll
        for (int i = 0; i < 2; ++i) {
            int idx = tid + i * NTHREADS;
            int n = idx >> 2, cc = idx & 3;
            cp_async16(sb + (n * SROWH + cc * 8) * 2, Bblk + (size_t)n * W1ROWS + kt * BK + cc * 8);
        }
    };

    // compute one k-tile from compile-time stage (direct LDS.32 fp16 fragments)
    auto compute_tile = [&](int stage) {
        const __half2* sa2 = reinterpret_cast<const __half2*>(smem + stage * STAGE_BYTES);
        const __half2* sb2 = reinterpret_cast<const __half2*>(smem + stage * STAGE_BYTES + A_STAGE_BYTES);
        const int S2 = SROWH / 2;   // 20 half2 per row
#pragma unroll
        for (int ks = 0; ks < 2; ++ks) {
            const int kh = ks * 8;                    // half2 column offset
            uint32_t b[4][2];
#pragma unroll
            for (int ni = 0; ni < 4; ++ni) {
                const int col = warpN * 32 + ni * 8 + gid;
                b[ni][0] = *reinterpret_cast<const uint32_t*>(&sb2[col * S2 + kh + tg]);
                b[ni][1] = *reinterpret_cast<const uint32_t*>(&sb2[col * S2 + kh + tg + 4]);
            }
#pragma unroll
            for (int mi = 0; mi < 4; ++mi) {
                const int r = warpM * 64 + mi * 16 + gid;
                uint32_t a0 = *reinterpret_cast<const uint32_t*>(&sa2[r * S2 + kh + tg]);
                uint32_t a1 = *reinterpret_cast<const uint32_t*>(&sa2[(r + 8) * S2 + kh + tg]);
                uint32_t a2 = *reinterpret_cast<const uint32_t*>(&sa2[r * S2 + kh + tg + 4]);
                uint32_t a3 = *reinterpret_cast<const uint32_t*>(&sa2[(r + 8) * S2 + kh + tg + 4]);
#pragma unroll
                for (int ni = 0; ni < 4; ++ni)
                    mma_f16(c[mi][ni][0], c[mi][ni][1], c[mi][ni][2], c[mi][ni][3],
                            a0, a1, a2, a3, b[ni][0], b[ni][1]);
            }
        }
    };

    load_tiles(0, 0); cp_commit();
    load_tiles(1, 1); cp_commit();

    // 24 tiles = 8 outer x 3 compile-time stages
    for (int kb = 0; kb < NKT / NSTAGE; ++kb) {
#pragma unroll
        for (int s = 0; s < NSTAGE; ++s) {
            const int kt = kb * NSTAGE + s;
            if (kt < NKT - 1) cp_wait<1>(); else cp_wait<0>();
            __syncthreads();
            if (kt + 2 < NKT) {
                load_tiles(kt + 2, (s + 2) % NSTAGE);   // compile-time stage
                cp_commit();
            }
            compute_tile(s);
        }
    }

    const int rowBase = blockIdx.y * BM + warpM * 64;
    const int colBase = blockIdx.x * BN + warpN * 32;

    if (MAIN) {
        float w2v[4][2];
#pragma unroll
        for (int ni = 0; ni < 4; ++ni) {
            w2v[ni][0] = __ldg(W2 + colBase + ni * 8 + tg * 2);
            w2v[ni][1] = __ldg(W2 + colBase + ni * 8 + tg * 2 + 1);
        }
#pragma unroll
        for (int mi = 0; mi < 4; ++mi)
#pragma unroll
            for (int rr = 0; rr < 2; ++rr) {
                const int prow = rowBase + mi * 16 + rr * 8 + gid;
                const int m = __ldg(midx + prow);
                const float* mp = g_Mpart + (size_t)m * HID;
                float acc = 0.f;
#pragma unroll
                for (int ni = 0; ni < 4; ++ni) {
                    const int col = colBase + ni * 8 + tg * 2;
                    float v0 = c[mi][ni][rr * 2]     + __ldg(mp + col);
                    float v1 = c[mi][ni][rr * 2 + 1] + __ldg(mp + col + 1);
                    acc = fmaf(fmaxf(v0, 0.f), w2v[ni][0], acc);
                    acc = fmaf(fmaxf(v1, 0.f), w2v[ni][1], acc);
                }
                acc += __shfl_xor_sync(0xffffffffu, acc, 1);
                acc += __shfl_xor_sync(0xffffffffu, acc, 2);
                if (tg == 0) {
                    if (blockIdx.x == 0 && warpN == 0) acc += __ldg(b2v);
                    atomicAdd(out + (size_t)m * (MAXK + 1) + __ldg(cidx + prow), acc);
                }
            }
    } else {
#pragma unroll
        for (int mi = 0; mi < 4; ++mi)
#pragma unroll
            for (int rr = 0; rr < 2; ++rr) {
                const int row = rowBase + mi * 16 + rr * 8 + gid;
#pragma unroll
                for (int ni = 0; ni < 4; ++ni) {
                    const int col = colBase + ni * 8 + tg * 2;
                    float2 v;
                    v.x = c[mi][ni][rr * 2]     + __ldg(b1 + col);
                    v.y = c[mi][ni][rr * 2 + 1] + __ldg(b1 + col + 1);
                    *reinterpret_cast<float2*>(&g_Mpart[(size_t)row * HID + col]) = v;
                }
            }
    }
}

// ---------------- launch ----------------
extern "C" void kernel_launch(void* const* d_in, const int* in_sizes, int n_in,
                              void* d_out, int out_size) {
    const float* mention = (const float*)d_in[0];  // [4096, 768]
    const float* cand    = (const float*)d_in[1];  // [131072, 768]
    const float* W1      = (const float*)d_in[2];  // [1536, 768]
    const float* b1      = (const float*)d_in[3];  // [768]
    const float* W2      = (const float*)d_in[4];  // [768, 1]
    const float* b2      = (const float*)d_in[5];  // [1]
    const float* prior   = (const float*)d_in[6];  // [4096, 64]
    const float* nota    = (const float*)d_in[7];  // []
    const int*   midx    = (const int*)d_in[8];    // [T]
    const int*   cidx    = (const int*)d_in[9];    // [T]
    float* out = (float*)d_out;                    // [4096, 65]

    const int N = in_sizes[0] / HID;   // 4096
    const int T = in_sizes[1] / HID;   // 131072

    __half* candH; cudaGetSymbolAddress((void**)&candH, g_candH);
    __half* mentH; cudaGetSymbolAddress((void**)&mentH, g_mentH);

    cudaFuncSetAttribute(gemm_kernel<false>, cudaFuncAttributeMaxDynamicSharedMemorySize, SMEM_BYTES);
    cudaFuncSetAttribute(gemm_kernel<true>,  cudaFuncAttributeMaxDynamicSharedMemorySize, SMEM_BYTES);

    // 0) out = 0.5*prior (+ nota col)
    init_out_kernel<<<(N * (MAXK + 1) + 255) / 256, 256>>>(out, prior, nota, N);

    // 1) fp16 conversions (coalesced streams) + W1 transpose
    long cand4 = (long)T * HID / 4;
    convert_kernel<<<(int)((cand4 + 255) / 256), 256>>>(cand, candH, cand4);
    long ment4 = (long)N * HID / 4;
    convert_kernel<<<(int)((ment4 + 255) / 256), 256>>>(mention, mentH, ment4);
    transpose_kernel<<<dim3(HID / 32, W1ROWS / 32), dim3(32, 8)>>>(W1);

    // 2) Mpart = mention @ W1_top + b1
    gemm_kernel<false><<<dim3(HID / BN, N / BM), NTHREADS, SMEM_BYTES>>>(
        mentH, 0, b1, W2, b2, nullptr, nullptr, out);

    // 3) fused: cand @ W1_bot -> +Mpart -> relu -> @W2 (+b2) -> scatter-add
    gemm_kernel<true><<<dim3(HID / BN, T / BM), NTHREADS, SMEM_BYTES>>>(
        candH, HID, b1, W2, b2, midx, cidx, out);
}

// round 12
// speedup vs baseline: 1.6371x; 1.0927x over previous
#include <cuda_runtime.h>
#include <cuda_fp16.h>
#include <cstdint>

// ---------------- problem constants ----------------
#define HID 768
#define W1ROWS 1536
#define MAXK 64
#define NMENT 4096
#define TPAIR 131072

// ---------------- tiling ----------------
#define BM 128
#define BN 128
#define BK 32                          // 32 k-halves per tile (2 mma k16 steps)
#define NKT (HID / BK)                 // 24 = 6 * NSTAGE
#define NTHREADS 256
#define SROWH 40                       // smem row stride in halves; LDSM rows partition banks
#define A_STAGE_BYTES (BM * SROWH * 2) // 10240
#define B_STAGE_BYTES (BN * SROWH * 2) // 10240
#define STAGE_BYTES (A_STAGE_BYTES + B_STAGE_BYTES)   // 20480
#define NSTAGE 4
#define SMEM_BYTES (NSTAGE * STAGE_BYTES)             // 81920 -> 2 CTAs/SM

// ---------------- device scratch (static, no allocs) ----------------
__device__ float  g_Mpart[NMENT * HID];          // mention @ W1_top + b1 (fp32)
__device__ __half g_W1TH[HID * W1ROWS];          // W1 transposed -> [n][k] fp16
__device__ __half g_candH[(size_t)TPAIR * HID];  // candidate embs fp16
__device__ __half g_mentH[NMENT * HID];          // mention embs fp16

// ---------------- helpers ----------------
__device__ __forceinline__ void cp_async16(void* sptr, const void* gptr) {
    uint32_t s = (uint32_t)__cvta_generic_to_shared(sptr);
    asm volatile("cp.async.cg.shared.global [%0], [%1], 16;\n" :: "r"(s), "l"(gptr));
}
__device__ __forceinline__ void cp_commit() { asm volatile("cp.async.commit_group;\n"); }
template <int W_>
__device__ __forceinline__ void cp_wait() { asm volatile("cp.async.wait_group %0;\n" :: "n"(W_)); }

__device__ __forceinline__ void mma_f16(float& c0, float& c1, float& c2, float& c3,
                                        uint32_t a0, uint32_t a1, uint32_t a2, uint32_t a3,
                                        uint32_t b0, uint32_t b1) {
    asm volatile(
        "mma.sync.aligned.m16n8k16.row.col.f32.f16.f16.f32 "
        "{%0,%1,%2,%3}, {%4,%5,%6,%7}, {%8,%9}, {%0,%1,%2,%3};\n"
        : "+f"(c0), "+f"(c1), "+f"(c2), "+f"(c3)
        : "r"(a0), "r"(a1), "r"(a2), "r"(a3), "r"(b0), "r"(b1));
}

__device__ __forceinline__ void ldsm_x4(uint32_t& r0, uint32_t& r1, uint32_t& r2, uint32_t& r3,
                                        uint32_t addr) {
    asm volatile("ldmatrix.sync.aligned.m8n8.x4.shared.b16 {%0,%1,%2,%3}, [%4];"
                 : "=r"(r0), "=r"(r1), "=r"(r2), "=r"(r3) : "r"(addr));
}

// ---------------- aux kernels ----------------
__global__ void init_out_kernel(float* __restrict__ out, const float* __restrict__ prior,
                                const float* __restrict__ nota, int n) {
    int i = blockIdx.x * blockDim.x + threadIdx.x;
    if (i < n * (MAXK + 1)) {
        int k = i % (MAXK + 1);
        int row = i / (MAXK + 1);
        out[i] = (k < MAXK) ? 0.5f * prior[row * MAXK + k] : nota[0];
    }
}

// fp32 -> fp16 stream convert (4 elems / thread, fully coalesced)
__global__ void convert_kernel(const float* __restrict__ src, __half* __restrict__ dst,
                               long n4) {
    long i = (long)blockIdx.x * blockDim.x + threadIdx.x;
    if (i < n4) {
        float4 v = *reinterpret_cast<const float4*>(src + i * 4);
        __half2 h0 = __floats2half2_rn(v.x, v.y);
        __half2 h1 = __floats2half2_rn(v.z, v.w);
        *reinterpret_cast<uint2*>(dst + i * 4) =
            make_uint2(*reinterpret_cast<uint32_t*>(&h0), *reinterpret_cast<uint32_t*>(&h1));
    }
}

// g_W1TH[n][k] = fp16(W1[k][n]);  W1: [1536, 768] row-major
__global__ void transpose_kernel(const float* __restrict__ W1) {
    __shared__ float t[32][33];
    int n0 = blockIdx.x * 32, k0 = blockIdx.y * 32;
    int tx = threadIdx.x, ty = threadIdx.y;
#pragma unroll
    for (int i = 0; i < 4; ++i)
        t[ty + 8 * i][tx] = W1[(size_t)(k0 + ty + 8 * i) * HID + n0 + tx];
    __syncthreads();
#pragma unroll
    for (int i = 0; i < 4; ++i)
        g_W1TH[(size_t)(n0 + ty + 8 * i) * W1ROWS + k0 + tx] = __float2half_rn(t[tx][ty + 8 * i]);
}

// ---------------- fp16 GEMM: cp.async feed + ldmatrix fragments, 2 CTAs/SM ----------------
// MAIN=false: g_Mpart = A @ W1T[:, kOff..]^T + b1
// MAIN=true : fused cand GEMM + Mpart gather + relu + W2 dot + scatter atomicAdd
template <bool MAIN>
__global__ __launch_bounds__(NTHREADS, 2)
void gemm_kernel(const __half* __restrict__ A, int kOff,
                 const float* __restrict__ b1, const float* __restrict__ W2,
                 const float* __restrict__ b2v,
                 const int* __restrict__ midx, const int* __restrict__ cidx,
                 float* __restrict__ out) {
    extern __shared__ char smem[];
    const uint32_t smemU = (uint32_t)__cvta_generic_to_shared(smem);

    const int tid   = threadIdx.x;
    const int warp  = tid >> 5;
    const int lane  = tid & 31;
    const int warpM = warp >> 2;          // 0..1  (64 rows)
    const int warpN = warp & 3;           // 0..3  (32 cols)
    const int gid   = lane >> 2;          // 0..7
    const int tg    = lane & 3;           // 0..3

    // ldmatrix per-lane address components (validated in round 8)
    const int lA  = lane & 15;                         // A row within 16
    const int kA8 = (lane >> 4) << 3;                  // A k-half offset 0/8
    const int rB  = ((lane >> 4) << 3) + (lane & 7);   // B row within 16
    const int kB8 = ((lane >> 3) & 1) << 3;            // B k-half offset 0/8

    const __half* Ablk = A + (size_t)blockIdx.y * BM * HID;
    const __half* Bblk = g_W1TH + (size_t)blockIdx.x * BN * W1ROWS + kOff;

    float c[4][4][4];
#pragma unroll
    for (int mi = 0; mi < 4; ++mi)
#pragma unroll
        for (int ni = 0; ni < 4; ++ni)
#pragma unroll
            for (int j = 0; j < 4; ++j) c[mi][ni][j] = 0.f;

    auto load_tiles = [&](int kt, int stage) {
        char* sa = smem + stage * STAGE_BYTES;
        char* sb = sa + A_STAGE_BYTES;
#pragma unroll
        for (int i = 0; i < 2; ++i) {                 // A: 128 rows x 4 x 16B (coalesced)
            int idx = tid + i * NTHREADS;
            int r = idx >> 2, cc = idx & 3;
            cp_async16(sa + (r * SROWH + cc * 8) * 2, Ablk + (size_t)r * HID + kt * BK + cc * 8);
        }
#pragma unroll
        for (int i = 0; i < 2; ++i) {                 // B: 128 rows x 4 x 16B
            int idx = tid + i * NTHREADS;
            int n = idx >> 2, cc = idx & 3;
            cp_async16(sb + (n * SROWH + cc * 8) * 2, Bblk + (size_t)n * W1ROWS + kt * BK + cc * 8);
        }
    };

    // compute one k-tile from compile-time stage (ldmatrix fragments)
    auto compute_tile = [&](int stage) {
        const uint32_t aOff = smemU + stage * STAGE_BYTES;
        const uint32_t bOff = aOff + A_STAGE_BYTES;
        const uint32_t aAddr0 = aOff + ((warpM * 64 + lA) * SROWH + kA8) * 2;
        const uint32_t bAddr0 = bOff + ((warpN * 32 + rB) * SROWH + kB8) * 2;
#pragma unroll
        for (int ks = 0; ks < 2; ++ks) {
            const int kf = ks * 16;
            uint32_t b[4][2];
            ldsm_x4(b[0][0], b[0][1], b[1][0], b[1][1], bAddr0 + kf * 2);
            ldsm_x4(b[2][0], b[2][1], b[3][0], b[3][1], bAddr0 + (16 * SROWH + kf) * 2);
#pragma unroll
            for (int mi = 0; mi < 4; ++mi) {
                uint32_t a0, a1, a2, a3;
                ldsm_x4(a0, a1, a2, a3, aAddr0 + (mi * 16 * SROWH + kf) * 2);
#pragma unroll
                for (int ni = 0; ni < 4; ++ni)
                    mma_f16(c[mi][ni][0], c[mi][ni][1], c[mi][ni][2], c[mi][ni][3],
                            a0, a1, a2, a3, b[ni][0], b[ni][1]);
            }
        }
    };

    load_tiles(0, 0); cp_commit();
    load_tiles(1, 1); cp_commit();
    load_tiles(2, 2); cp_commit();

    // 24 tiles = 6 outer x 4 compile-time stages
    for (int kb = 0; kb < NKT / NSTAGE; ++kb) {
#pragma unroll
        for (int s = 0; s < NSTAGE; ++s) {
            const int kt = kb * NSTAGE + s;
            if (kt < NKT - 2) cp_wait<2>();
            else if (kt < NKT - 1) cp_wait<1>();
            else cp_wait<0>();
            __syncthreads();
            if (kt + 3 < NKT) {
                load_tiles(kt + 3, (s + 3) % NSTAGE);   // compile-time stage
                cp_commit();
            }
            compute_tile(s);
        }
    }

    const int rowBase = blockIdx.y * BM + warpM * 64;
    const int colBase = blockIdx.x * BN + warpN * 32;

    if (MAIN) {
        float w2v[4][2];
#pragma unroll
        for (int ni = 0; ni < 4; ++ni) {
            w2v[ni][0] = __ldg(W2 + colBase + ni * 8 + tg * 2);
            w2v[ni][1] = __ldg(W2 + colBase + ni * 8 + tg * 2 + 1);
        }
#pragma unroll
        for (int mi = 0; mi < 4; ++mi)
#pragma unroll
            for (int rr = 0; rr < 2; ++rr) {
                const int prow = rowBase + mi * 16 + rr * 8 + gid;
                const int m = __ldg(midx + prow);
                const float* mp = g_Mpart + (size_t)m * HID;
                float acc = 0.f;
#pragma unroll
                for (int ni = 0; ni < 4; ++ni) {
                    const int col = colBase + ni * 8 + tg * 2;
                    float v0 = c[mi][ni][rr * 2]     + __ldg(mp + col);
                    float v1 = c[mi][ni][rr * 2 + 1] + __ldg(mp + col + 1);
                    acc = fmaf(fmaxf(v0, 0.f), w2v[ni][0], acc);
                    acc = fmaf(fmaxf(v1, 0.f), w2v[ni][1], acc);
                }
                acc += __shfl_xor_sync(0xffffffffu, acc, 1);
                acc += __shfl_xor_sync(0xffffffffu, acc, 2);
                if (tg == 0) {
                    if (blockIdx.x == 0 && warpN == 0) acc += __ldg(b2v);
                    atomicAdd(out + (size_t)m * (MAXK + 1) + __ldg(cidx + prow), acc);
                }
            }
    } else {
#pragma unroll
        for (int mi = 0; mi < 4; ++mi)
#pragma unroll
            for (int rr = 0; rr < 2; ++rr) {
                const int row = rowBase + mi * 16 + rr * 8 + gid;
#pragma unroll
                for (int ni = 0; ni < 4; ++ni) {
                    const int col = colBase + ni * 8 + tg * 2;
                    float2 v;
                    v.x = c[mi][ni][rr * 2]     + __ldg(b1 + col);
                    v.y = c[mi][ni][rr * 2 + 1] + __ldg(b1 + col + 1);
                    *reinterpret_cast<float2*>(&g_Mpart[(size_t)row * HID + col]) = v;
                }
            }
    }
}

// ---------------- launch ----------------
extern "C" void kernel_launch(void* const* d_in, const int* in_sizes, int n_in,
                              void* d_out, int out_size) {
    const float* mention = (const float*)d_in[0];  // [4096, 768]
    const float* cand    = (const float*)d_in[1];  // [131072, 768]
    const float* W1      = (const float*)d_in[2];  // [1536, 768]
    const float* b1      = (const float*)d_in[3];  // [768]
    const float* W2      = (const float*)d_in[4];  // [768, 1]
    const float* b2      = (const float*)d_in[5];  // [1]
    const float* prior   = (const float*)d_in[6];  // [4096, 64]
    const float* nota    = (const float*)d_in[7];  // []
    const int*   midx    = (const int*)d_in[8];    // [T]
    const int*   cidx    = (const int*)d_in[9];    // [T]
    float* out = (float*)d_out;                    // [4096, 65]

    const int N = in_sizes[0] / HID;   // 4096
    const int T = in_sizes[1] / HID;   // 131072

    __half* candH; cudaGetSymbolAddress((void**)&candH, g_candH);
    __half* mentH; cudaGetSymbolAddress((void**)&mentH, g_mentH);

    cudaFuncSetAttribute(gemm_kernel<false>, cudaFuncAttributeMaxDynamicSharedMemorySize, SMEM_BYTES);
    cudaFuncSetAttribute(gemm_kernel<true>,  cudaFuncAttributeMaxDynamicSharedMemorySize, SMEM_BYTES);

    // 0) out = 0.5*prior (+ nota col)
    init_out_kernel<<<(N * (MAXK + 1) + 255) / 256, 256>>>(out, prior, nota, N);

    // 1) fp16 conversions (coalesced streams) + W1 transpose
    long cand4 = (long)T * HID / 4;
    convert_kernel<<<(int)((cand4 + 255) / 256), 256>>>(cand, candH, cand4);
    long ment4 = (long)N * HID / 4;
    convert_kernel<<<(int)((ment4 + 255) / 256), 256>>>(mention, mentH, ment4);
    transpose_kernel<<<dim3(HID / 32, W1ROWS / 32), dim3(32, 8)>>>(W1);

    // 2) Mpart = mention @ W1_top + b1
    gemm_kernel<false><<<dim3(HID / BN, N / BM), NTHREADS, SMEM_BYTES>>>(
        mentH, 0, b1, W2, b2, nullptr, nullptr, out);

    // 3) fused: cand @ W1_bot -> +Mpart -> relu -> @W2 (+b2) -> scatter-add
    gemm_kernel<true><<<dim3(HID / BN, T / BM), NTHREADS, SMEM_BYTES>>>(
        candH, HID, b1, W2, b2, midx, cidx, out);
}

// round 13
// speedup vs baseline: 1.8852x; 1.1515x over previous
#include <cuda_runtime.h>
#include <cuda_fp16.h>
#include <cstdint>

// ---------------- problem constants ----------------
#define HID 768
#define W1ROWS 1536
#define MAXK 64
#define NMENT 4096

// ---------------- tiling ----------------
#define BM 128
#define BN 128
#define BK 32                          // 32 k-halves per tile (2 mma k16 steps)
#define NKT (HID / BK)                 // 24 = 6 * NSTAGE
#define NTHREADS 256
// A/B tiles: 64-byte rows (32 halves, no pad) + XOR-16B swizzle: chunk ^= (row>>1)&3
#define ROWB 64                        // bytes per smem row
#define A_STAGE_BYTES (BM * ROWB)      // 8192
#define B_STAGE_BYTES (BN * ROWB)      // 8192
#define STAGE_BYTES (A_STAGE_BYTES + B_STAGE_BYTES)   // 16384
#define NSTAGE 4
#define SMEM_BYTES (NSTAGE * STAGE_BYTES)             // 65536 -> 2 CTAs/SM

// ---------------- device scratch (static, no allocs) ----------------
__device__ float  g_Mpart[NMENT * HID];     // mention @ W1_top + b1 (fp32)
__device__ __half g_W1TH[HID * W1ROWS];     // W1 transposed -> [n][k] fp16

// ---------------- helpers ----------------
__device__ __forceinline__ void cp_async16(void* sptr, const void* gptr) {
    uint32_t s = (uint32_t)__cvta_generic_to_shared(sptr);
    asm volatile("cp.async.cg.shared.global [%0], [%1], 16;\n" :: "r"(s), "l"(gptr));
}
__device__ __forceinline__ void cp_commit() { asm volatile("cp.async.commit_group;\n"); }
template <int W_>
__device__ __forceinline__ void cp_wait() { asm volatile("cp.async.wait_group %0;\n" :: "n"(W_)); }

__device__ __forceinline__ void mma_f16(float& c0, float& c1, float& c2, float& c3,
                                        uint32_t a0, uint32_t a1, uint32_t a2, uint32_t a3,
                                        uint32_t b0, uint32_t b1) {
    asm volatile(
        "mma.sync.aligned.m16n8k16.row.col.f32.f16.f16.f32 "
        "{%0,%1,%2,%3}, {%4,%5,%6,%7}, {%8,%9}, {%0,%1,%2,%3};\n"
        : "+f"(c0), "+f"(c1), "+f"(c2), "+f"(c3)
        : "r"(a0), "r"(a1), "r"(a2), "r"(a3), "r"(b0), "r"(b1));
}

__device__ __forceinline__ void ldsm_x4(uint32_t& r0, uint32_t& r1, uint32_t& r2, uint32_t& r3,
                                        uint32_t addr) {
    asm volatile("ldmatrix.sync.aligned.m8n8.x4.shared.b16 {%0,%1,%2,%3}, [%4];"
                 : "=r"(r0), "=r"(r1), "=r"(r2), "=r"(r3) : "r"(addr));
}

__device__ __forceinline__ uint32_t f2h2(float x, float y) {
    __half2 h = __floats2half2_rn(x, y);
    return *reinterpret_cast<uint32_t*>(&h);
}

// ---------------- aux kernels ----------------
__global__ void init_out_kernel(float* __restrict__ out, const float* __restrict__ prior,
                                const float* __restrict__ nota, int n) {
    int i = blockIdx.x * blockDim.x + threadIdx.x;
    if (i < n * (MAXK + 1)) {
        int k = i % (MAXK + 1);
        int row = i / (MAXK + 1);
        out[i] = (k < MAXK) ? 0.5f * prior[row * MAXK + k] : nota[0];
    }
}

// g_W1TH[n][k] = fp16(W1[k][n]);  W1: [1536, 768] row-major
__global__ void transpose_kernel(const float* __restrict__ W1) {
    __shared__ float t[32][33];
    int n0 = blockIdx.x * 32, k0 = blockIdx.y * 32;
    int tx = threadIdx.x, ty = threadIdx.y;
#pragma unroll
    for (int i = 0; i < 4; ++i)
        t[ty + 8 * i][tx] = W1[(size_t)(k0 + ty + 8 * i) * HID + n0 + tx];
    __syncthreads();
#pragma unroll
    for (int i = 0; i < 4; ++i)
        g_W1TH[(size_t)(n0 + ty + 8 * i) * W1ROWS + k0 + tx] = __float2half_rn(t[tx][ty + 8 * i]);
}

// ---------------- fp16 GEMM: fp32 A in-kernel convert, swizzled smem, ldmatrix ----------
// MAIN=false: g_Mpart = A @ W1T[:, kOff..]^T + b1
// MAIN=true : fused cand GEMM + Mpart gather + relu + W2 dot + scatter atomicAdd
template <bool MAIN>
__global__ __launch_bounds__(NTHREADS, 2)
void gemm_kernel(const float* __restrict__ A, int kOff,
                 const float* __restrict__ b1, const float* __restrict__ W2,
                 const float* __restrict__ b2v,
                 const int* __restrict__ midx, const int* __restrict__ cidx,
                 float* __restrict__ out) {
    extern __shared__ char smem[];
    const uint32_t smemU = (uint32_t)__cvta_generic_to_shared(smem);

    const int tid   = threadIdx.x;
    const int warp  = tid >> 5;
    const int lane  = tid & 31;
    const int warpM = warp >> 2;          // 0..1  (64 rows)
    const int warpN = warp & 3;           // 0..3  (32 cols)
    const int gid   = lane >> 2;          // 0..7
    const int tg    = lane & 3;           // 0..3

    // ldmatrix per-lane components (+ row-derived XOR swizzle, invariant over mi/ks)
    const int lA   = lane & 15;                        // A row within 16
    const int hiA  = lane >> 4;                        // A k-chunk bit (0/1)
    const int swzA = (lA >> 1) & 3;
    const int rB   = ((lane >> 4) << 3) + (lane & 7);  // B row within 32 (warp slice)
    const int hiB  = (lane >> 3) & 1;                  // B k-chunk bit
    const int swzB = ((lane & 7) >> 1) & 3;

    // A loader: idx -> row=idx>>2 (4 threads/row), chunk=idx&3 (8 floats each)
    const float*  Ablk = A + (size_t)blockIdx.y * BM * HID;
    const __half* Bblk = g_W1TH + (size_t)blockIdx.x * BN * W1ROWS + kOff;

    float c[4][4][4];
#pragma unroll
    for (int mi = 0; mi < 4; ++mi)
#pragma unroll
        for (int ni = 0; ni < 4; ++ni)
#pragma unroll
            for (int j = 0; j < 4; ++j) c[mi][ni][j] = 0.f;

    // ---- A path: coalesced LDG(fp32) -> CVT -> swizzled STS.128 ----
    auto ldgA = [&](int kt, float4* f) {
#pragma unroll
        for (int i = 0; i < 2; ++i) {
            int idx = tid + i * NTHREADS;           // 512 row-chunks
            int r = idx >> 2, cc = idx & 3;
            const float* p = Ablk + (size_t)r * HID + kt * BK + cc * 8;
            f[i * 2]     = *reinterpret_cast<const float4*>(p);
            f[i * 2 + 1] = *reinterpret_cast<const float4*>(p + 4);
        }
    };
    auto stsA = [&](int stage, const float4* f) {
#pragma unroll
        for (int i = 0; i < 2; ++i) {
            int idx = tid + i * NTHREADS;
            int r = idx >> 2, cc = idx & 3;
            int pc = cc ^ ((r >> 1) & 3);            // swizzled 16B chunk
            uint4 h;
            h.x = f2h2(f[i * 2].x,     f[i * 2].y);
            h.y = f2h2(f[i * 2].z,     f[i * 2].w);
            h.z = f2h2(f[i * 2 + 1].x, f[i * 2 + 1].y);
            h.w = f2h2(f[i * 2 + 1].z, f[i * 2 + 1].w);
            *reinterpret_cast<uint4*>(smem + stage * STAGE_BYTES + r * ROWB + pc * 16) = h;
        }
    };
    // ---- B path: cp.async into swizzled layout ----
    auto loadB = [&](int kt, int stage) {
        char* sb = smem + stage * STAGE_BYTES + A_STAGE_BYTES;
#pragma unroll
        for (int i = 0; i < 2; ++i) {
            int idx = tid + i * NTHREADS;
            int n = idx >> 2, cc = idx & 3;
            int pc = cc ^ ((n >> 1) & 3);
            cp_async16(sb + n * ROWB + pc * 16, Bblk + (size_t)n * W1ROWS + kt * BK + cc * 8);
        }
    };

    // compute one k-tile from compile-time stage (swizzled ldmatrix fragments)
    auto compute_tile = [&](int stage) {
        const uint32_t aOff = smemU + stage * STAGE_BYTES;
        const uint32_t bOff = aOff + A_STAGE_BYTES;
        const uint32_t aRow = aOff + (uint32_t)(warpM * 64 + lA) * ROWB;
        const uint32_t bRow = bOff + (uint32_t)(warpN * 32 + rB) * ROWB;
#pragma unroll
        for (int ks = 0; ks < 2; ++ks) {
            const uint32_t aAddr = aRow + (uint32_t)(((ks * 2 + hiA) ^ swzA) * 16);
            const uint32_t bAddr = bRow + (uint32_t)(((ks * 2 + hiB) ^ swzB) * 16);
            uint32_t b[4][2];
            ldsm_x4(b[0][0], b[0][1], b[1][0], b[1][1], bAddr);
            ldsm_x4(b[2][0], b[2][1], b[3][0], b[3][1], bAddr + 16 * ROWB);
#pragma unroll
            for (int mi = 0; mi < 4; ++mi) {
                uint32_t a0, a1, a2, a3;
                ldsm_x4(a0, a1, a2, a3, aAddr + mi * 16 * ROWB);
#pragma unroll
                for (int ni = 0; ni < 4; ++ni)
                    mma_f16(c[mi][ni][0], c[mi][ni][1], c[mi][ni][2], c[mi][ni][3],
                            a0, a1, a2, a3, b[ni][0], b[ni][1]);
            }
        }
    };

    // prolog: fill stages 0..2
    {
        float4 f[4];
        ldgA(0, f); stsA(0, f);
        ldgA(1, f); stsA(1, f);
        ldgA(2, f); stsA(2, f);
    }
    loadB(0, 0); cp_commit();
    loadB(1, 1); cp_commit();
    loadB(2, 2); cp_commit();

    float4 fbuf[4];
    // 24 tiles = 6 outer x 4 compile-time stages
    for (int kb = 0; kb < NKT / NSTAGE; ++kb) {
#pragma unroll
        for (int s = 0; s < NSTAGE; ++s) {
            const int kt = kb * NSTAGE + s;
            if (kt < NKT - 2) cp_wait<2>();
            else if (kt < NKT - 1) cp_wait<1>();
            else cp_wait<0>();
            __syncthreads();
            if (kt + 3 < NKT) {
                ldgA(kt + 3, fbuf);                    // long-latency fetch up front
                loadB(kt + 3, (s + 3) % NSTAGE);
                cp_commit();
            }
            compute_tile(s);
            if (kt + 3 < NKT) stsA((s + 3) % NSTAGE, fbuf);  // slot last read at kt-1
        }
    }

    const int rowBase = blockIdx.y * BM + warpM * 64;
    const int colBase = blockIdx.x * BN + warpN * 32;

    if (MAIN) {
        float w2v[4][2];
#pragma unroll
        for (int ni = 0; ni < 4; ++ni) {
            w2v[ni][0] = __ldg(W2 + colBase + ni * 8 + tg * 2);
            w2v[ni][1] = __ldg(W2 + colBase + ni * 8 + tg * 2 + 1);
        }
#pragma unroll
        for (int mi = 0; mi < 4; ++mi)
#pragma unroll
            for (int rr = 0; rr < 2; ++rr) {
                const int prow = rowBase + mi * 16 + rr * 8 + gid;
                const int m = __ldg(midx + prow);
                const float* mp = g_Mpart + (size_t)m * HID;
                float acc = 0.f;
#pragma unroll
                for (int ni = 0; ni < 4; ++ni) {
                    const int col = colBase + ni * 8 + tg * 2;
                    float v0 = c[mi][ni][rr * 2]     + __ldg(mp + col);
                    float v1 = c[mi][ni][rr * 2 + 1] + __ldg(mp + col + 1);
                    acc = fmaf(fmaxf(v0, 0.f), w2v[ni][0], acc);
                    acc = fmaf(fmaxf(v1, 0.f), w2v[ni][1], acc);
                }
                acc += __shfl_xor_sync(0xffffffffu, acc, 1);
                acc += __shfl_xor_sync(0xffffffffu, acc, 2);
                if (tg == 0) {
                    if (blockIdx.x == 0 && warpN == 0) acc += __ldg(b2v);
                    atomicAdd(out + (size_t)m * (MAXK + 1) + __ldg(cidx + prow), acc);
                }
            }
    } else {
#pragma unroll
        for (int mi = 0; mi < 4; ++mi)
#pragma unroll
            for (int rr = 0; rr < 2; ++rr) {
                const int row = rowBase + mi * 16 + rr * 8 + gid;
#pragma unroll
                for (int ni = 0; ni < 4; ++ni) {
                    const int col = colBase + ni * 8 + tg * 2;
                    float2 v;
                    v.x = c[mi][ni][rr * 2]     + __ldg(b1 + col);
                    v.y = c[mi][ni][rr * 2 + 1] + __ldg(b1 + col + 1);
                    *reinterpret_cast<float2*>(&g_Mpart[(size_t)row * HID + col]) = v;
                }
            }
    }
}

// ---------------- launch ----------------
extern "C" void kernel_launch(void* const* d_in, const int* in_sizes, int n_in,
                              void* d_out, int out_size) {
    const float* mention = (const float*)d_in[0];  // [4096, 768]
    const float* cand    = (const float*)d_in[1];  // [131072, 768]
    const float* W1      = (const float*)d_in[2];  // [1536, 768]
    const float* b1      = (const float*)d_in[3];  // [768]
    const float* W2      = (const float*)d_in[4];  // [768, 1]
    const float* b2      = (const float*)d_in[5];  // [1]
    const float* prior   = (const float*)d_in[6];  // [4096, 64]
    const float* nota    = (const float*)d_in[7];  // []
    const int*   midx    = (const int*)d_in[8];    // [T]
    const int*   cidx    = (const int*)d_in[9];    // [T]
    float* out = (float*)d_out;                    // [4096, 65]

    const int N = in_sizes[0] / HID;   // 4096
    const int T = in_sizes[1] / HID;   // 131072

    cudaFuncSetAttribute(gemm_kernel<false>, cudaFuncAttributeMaxDynamicSharedMemorySize, SMEM_BYTES);
    cudaFuncSetAttribute(gemm_kernel<true>,  cudaFuncAttributeMaxDynamicSharedMemorySize, SMEM_BYTES);

    // 0) out = 0.5*prior (+ nota col)
    init_out_kernel<<<(N * (MAXK + 1) + 255) / 256, 256>>>(out, prior, nota, N);

    // 1) W1T (fp16) = W1^T
    transpose_kernel<<<dim3(HID / 32, W1ROWS / 32), dim3(32, 8)>>>(W1);

    // 2) Mpart = mention @ W1_top + b1
    gemm_kernel<false><<<dim3(HID / BN, N / BM), NTHREADS, SMEM_BYTES>>>(
        mention, 0, b1, W2, b2, nullptr, nullptr, out);

    // 3) fused: cand @ W1_bot -> +Mpart -> relu -> @W2 (+b2) -> scatter-add
    gemm_kernel<true><<<dim3(HID / BN, T / BM), NTHREADS, SMEM_BYTES>>>(
        cand, HID, b1, W2, b2, midx, cidx, out);
}

// round 14
// speedup vs baseline: 2.0500x; 1.0874x over previous
#include <cuda_runtime.h>
#include <cuda_fp16.h>
#include <cstdint>

// ---------------- problem constants ----------------
#define HID 768
#define W1ROWS 1536
#define MAXK 64
#define NMENT 4096

// ---------------- tiling ----------------
#define BM 128
#define BN 128
#define BK 32                          // 32 k-halves per tile (2 mma k16 steps)
#define NKT (HID / BK)                 // 24 = 6 * NSTAGE
#define NTHREADS 256
// A/B tiles: 64-byte rows (32 halves, no pad) + XOR-16B swizzle: chunk ^= (row>>1)&3
#define ROWB 64                        // bytes per smem row
#define A_STAGE_BYTES (BM * ROWB)      // 8192
#define B_STAGE_BYTES (BN * ROWB)      // 8192
#define STAGE_BYTES (A_STAGE_BYTES + B_STAGE_BYTES)   // 16384
#define NSTAGE 4
#define SMEM_BYTES (NSTAGE * STAGE_BYTES)             // 65536 -> 2 CTAs/SM

// ---------------- device scratch (static, no allocs) ----------------
__device__ float  g_Mpart[NMENT * HID];     // mention @ W1_top + b1 (fp32)
__device__ __half g_W1TH[HID * W1ROWS];     // W1 transposed -> [n][k] fp16

// ---------------- helpers ----------------
__device__ __forceinline__ void cp_async16(void* sptr, const void* gptr) {
    uint32_t s = (uint32_t)__cvta_generic_to_shared(sptr);
    asm volatile("cp.async.cg.shared.global [%0], [%1], 16;\n" :: "r"(s), "l"(gptr));
}
__device__ __forceinline__ void cp_commit() { asm volatile("cp.async.commit_group;\n"); }
template <int W_>
__device__ __forceinline__ void cp_wait() { asm volatile("cp.async.wait_group %0;\n" :: "n"(W_)); }

__device__ __forceinline__ void mma_f16(float& c0, float& c1, float& c2, float& c3,
                                        uint32_t a0, uint32_t a1, uint32_t a2, uint32_t a3,
                                        uint32_t b0, uint32_t b1) {
    asm volatile(
        "mma.sync.aligned.m16n8k16.row.col.f32.f16.f16.f32 "
        "{%0,%1,%2,%3}, {%4,%5,%6,%7}, {%8,%9}, {%0,%1,%2,%3};\n"
        : "+f"(c0), "+f"(c1), "+f"(c2), "+f"(c3)
        : "r"(a0), "r"(a1), "r"(a2), "r"(a3), "r"(b0), "r"(b1));
}

__device__ __forceinline__ void ldsm_x4(uint32_t& r0, uint32_t& r1, uint32_t& r2, uint32_t& r3,
                                        uint32_t addr) {
    asm volatile("ldmatrix.sync.aligned.m8n8.x4.shared.b16 {%0,%1,%2,%3}, [%4];"
                 : "=r"(r0), "=r"(r1), "=r"(r2), "=r"(r3) : "r"(addr));
}

__device__ __forceinline__ uint32_t f2h2(float x, float y) {
    __half2 h = __floats2half2_rn(x, y);
    return *reinterpret_cast<uint32_t*>(&h);
}

// ---------------- aux kernels ----------------
__global__ void init_out_kernel(float* __restrict__ out, const float* __restrict__ prior,
                                const float* __restrict__ nota, int n) {
    int i = blockIdx.x * blockDim.x + threadIdx.x;
    if (i < n * (MAXK + 1)) {
        int k = i % (MAXK + 1);
        int row = i / (MAXK + 1);
        out[i] = (k < MAXK) ? 0.5f * prior[row * MAXK + k] : nota[0];
    }
}

// g_W1TH[n][k] = fp16(W1[k][n]);  W1: [1536, 768] row-major
__global__ void transpose_kernel(const float* __restrict__ W1) {
    __shared__ float t[32][33];
    int n0 = blockIdx.x * 32, k0 = blockIdx.y * 32;
    int tx = threadIdx.x, ty = threadIdx.y;
#pragma unroll
    for (int i = 0; i < 4; ++i)
        t[ty + 8 * i][tx] = W1[(size_t)(k0 + ty + 8 * i) * HID + n0 + tx];
    __syncthreads();
#pragma unroll
    for (int i = 0; i < 4; ++i)
        g_W1TH[(size_t)(n0 + ty + 8 * i) * W1ROWS + k0 + tx] = __float2half_rn(t[tx][ty + 8 * i]);
}

// ---------------- fp16 GEMM: in-kernel A convert, swizzled smem, ldmatrix ----------
// stsA hoisted to tile-body top (STS drains under compute, not under the barrier).
// MAIN=false: g_Mpart = A @ W1T[:, kOff..]^T + b1
// MAIN=true : fused cand GEMM + Mpart gather + relu + W2 dot + scatter atomicAdd
template <bool MAIN>
__global__ __launch_bounds__(NTHREADS, 2)
void gemm_kernel(const float* __restrict__ A, int kOff,
                 const float* __restrict__ b1, const float* __restrict__ W2,
                 const float* __restrict__ b2v,
                 const int* __restrict__ midx, const int* __restrict__ cidx,
                 float* __restrict__ out) {
    extern __shared__ char smem[];
    const uint32_t smemU = (uint32_t)__cvta_generic_to_shared(smem);

    const int tid   = threadIdx.x;
    const int warp  = tid >> 5;
    const int lane  = tid & 31;
    const int warpM = warp >> 2;          // 0..1  (64 rows)
    const int warpN = warp & 3;           // 0..3  (32 cols)
    const int gid   = lane >> 2;          // 0..7
    const int tg    = lane & 3;           // 0..3

    // ldmatrix per-lane components (+ row-derived XOR swizzle, invariant over mi/ks)
    const int lA   = lane & 15;                        // A row within 16
    const int hiA  = lane >> 4;                        // A k-chunk bit (0/1)
    const int swzA = (lA >> 1) & 3;
    const int rB   = ((lane >> 4) << 3) + (lane & 7);  // B row within 32 (warp slice)
    const int hiB  = (lane >> 3) & 1;                  // B k-chunk bit
    const int swzB = ((lane & 7) >> 1) & 3;

    const float*  Ablk = A + (size_t)blockIdx.y * BM * HID;
    const __half* Bblk = g_W1TH + (size_t)blockIdx.x * BN * W1ROWS + kOff;

    float c[4][4][4];
#pragma unroll
    for (int mi = 0; mi < 4; ++mi)
#pragma unroll
        for (int ni = 0; ni < 4; ++ni)
#pragma unroll
            for (int j = 0; j < 4; ++j) c[mi][ni][j] = 0.f;

    // ---- A path: coalesced LDG(fp32) -> CVT -> swizzled STS.128 ----
    auto ldgA = [&](int kt, float4* f) {
#pragma unroll
        for (int i = 0; i < 2; ++i) {
            int idx = tid + i * NTHREADS;           // 512 row-chunks
            int r = idx >> 2, cc = idx & 3;
            const float* p = Ablk + (size_t)r * HID + kt * BK + cc * 8;
            f[i * 2]     = *reinterpret_cast<const float4*>(p);
            f[i * 2 + 1] = *reinterpret_cast<const float4*>(p + 4);
        }
    };
    auto stsA = [&](int stage, const float4* f) {
#pragma unroll
        for (int i = 0; i < 2; ++i) {
            int idx = tid + i * NTHREADS;
            int r = idx >> 2, cc = idx & 3;
            int pc = cc ^ ((r >> 1) & 3);            // swizzled 16B chunk
            uint4 h;
            h.x = f2h2(f[i * 2].x,     f[i * 2].y);
            h.y = f2h2(f[i * 2].z,     f[i * 2].w);
            h.z = f2h2(f[i * 2 + 1].x, f[i * 2 + 1].y);
            h.w = f2h2(f[i * 2 + 1].z, f[i * 2 + 1].w);
            *reinterpret_cast<uint4*>(smem + stage * STAGE_BYTES + r * ROWB + pc * 16) = h;
        }
    };
    // ---- B path: cp.async into swizzled layout ----
    auto loadB = [&](int kt, int stage) {
        char* sb = smem + stage * STAGE_BYTES + A_STAGE_BYTES;
#pragma unroll
        for (int i = 0; i < 2; ++i) {
            int idx = tid + i * NTHREADS;
            int n = idx >> 2, cc = idx & 3;
            int pc = cc ^ ((n >> 1) & 3);
            cp_async16(sb + n * ROWB + pc * 16, Bblk + (size_t)n * W1ROWS + kt * BK + cc * 8);
        }
    };

    // compute one k-tile from compile-time stage (swizzled ldmatrix fragments)
    auto compute_tile = [&](int stage) {
        const uint32_t aOff = smemU + stage * STAGE_BYTES;
        const uint32_t bOff = aOff + A_STAGE_BYTES;
        const uint32_t aRow = aOff + (uint32_t)(warpM * 64 + lA) * ROWB;
        const uint32_t bRow = bOff + (uint32_t)(warpN * 32 + rB) * ROWB;
#pragma unroll
        for (int ks = 0; ks < 2; ++ks) {
            const uint32_t aAddr = aRow + (uint32_t)(((ks * 2 + hiA) ^ swzA) * 16);
            const uint32_t bAddr = bRow + (uint32_t)(((ks * 2 + hiB) ^ swzB) * 16);
            uint32_t b[4][2];
            ldsm_x4(b[0][0], b[0][1], b[1][0], b[1][1], bAddr);
            ldsm_x4(b[2][0], b[2][1], b[3][0], b[3][1], bAddr + 16 * ROWB);
#pragma unroll
            for (int mi = 0; mi < 4; ++mi) {
                uint32_t a0, a1, a2, a3;
                ldsm_x4(a0, a1, a2, a3, aAddr + mi * 16 * ROWB);
#pragma unroll
                for (int ni = 0; ni < 4; ++ni)
                    mma_f16(c[mi][ni][0], c[mi][ni][1], c[mi][ni][2], c[mi][ni][3],
                            a0, a1, a2, a3, b[ni][0], b[ni][1]);
            }
        }
    };

    // prolog: A stages 0,1 stored; A(2) parked in fbuf; B stages 0..2 in flight
    float4 fbuf[4];
    {
        float4 f[4];
        ldgA(0, f); stsA(0, f);
        ldgA(1, f); stsA(1, f);
    }
    ldgA(2, fbuf);
    loadB(0, 0); cp_commit();
    loadB(1, 1); cp_commit();
    loadB(2, 2); cp_commit();

    // 24 tiles = 6 outer x 4 compile-time stages
    for (int kb = 0; kb < NKT / NSTAGE; ++kb) {
#pragma unroll
        for (int s = 0; s < NSTAGE; ++s) {
            const int kt = kb * NSTAGE + s;
            if (kt < NKT - 2) cp_wait<2>();
            else if (kt < NKT - 1) cp_wait<1>();
            else cp_wait<0>();
            __syncthreads();
            // STS the parked A(kt+2) now — drains under this tile's compute,
            // not under the next barrier. Stage (s+2)%4 last read at kt-2: safe.
            if (kt + 2 < NKT) stsA((s + 2) % NSTAGE, fbuf);
            if (kt + 3 < NKT) {
                ldgA(kt + 3, fbuf);                    // full compute-span to land
                loadB(kt + 3, (s + 3) % NSTAGE);
                cp_commit();
            }
            compute_tile(s);
        }
    }

    const int rowBase = blockIdx.y * BM + warpM * 64;
    const int colBase = blockIdx.x * BN + warpN * 32;

    if (MAIN) {
        float w2v[4][2];
#pragma unroll
        for (int ni = 0; ni < 4; ++ni) {
            w2v[ni][0] = __ldg(W2 + colBase + ni * 8 + tg * 2);
            w2v[ni][1] = __ldg(W2 + colBase + ni * 8 + tg * 2 + 1);
        }
#pragma unroll
        for (int mi = 0; mi < 4; ++mi)
#pragma unroll
            for (int rr = 0; rr < 2; ++rr) {
                const int prow = rowBase + mi * 16 + rr * 8 + gid;
                const int m = __ldg(midx + prow);
                const float* mp = g_Mpart + (size_t)m * HID;
                float acc = 0.f;
#pragma unroll
                for (int ni = 0; ni < 4; ++ni) {
                    const int col = colBase + ni * 8 + tg * 2;
                    float v0 = c[mi][ni][rr * 2]     + __ldg(mp + col);
                    float v1 = c[mi][ni][rr * 2 + 1] + __ldg(mp + col + 1);
                    acc = fmaf(fmaxf(v0, 0.f), w2v[ni][0], acc);
                    acc = fmaf(fmaxf(v1, 0.f), w2v[ni][1], acc);
                }
                acc += __shfl_xor_sync(0xffffffffu, acc, 1);
                acc += __shfl_xor_sync(0xffffffffu, acc, 2);
                if (tg == 0) {
                    if (blockIdx.x == 0 && warpN == 0) acc += __ldg(b2v);
                    atomicAdd(out + (size_t)m * (MAXK + 1) + __ldg(cidx + prow), acc);
                }
            }
    } else {
#pragma unroll
        for (int mi = 0; mi < 4; ++mi)
#pragma unroll
            for (int rr = 0; rr < 2; ++rr) {
                const int row = rowBase + mi * 16 + rr * 8 + gid;
#pragma unroll
                for (int ni = 0; ni < 4; ++ni) {
                    const int col = colBase + ni * 8 + tg * 2;
                    float2 v;
                    v.x = c[mi][ni][rr * 2]     + __ldg(b1 + col);
                    v.y = c[mi][ni][rr * 2 + 1] + __ldg(b1 + col + 1);
                    *reinterpret_cast<float2*>(&g_Mpart[(size_t)row * HID + col]) = v;
                }
            }
    }
}

// ---------------- launch ----------------
extern "C" void kernel_launch(void* const* d_in, const int* in_sizes, int n_in,
                              void* d_out, int out_size) {
    const float* mention = (const float*)d_in[0];  // [4096, 768]
    const float* cand    = (const float*)d_in[1];  // [131072, 768]
    const float* W1      = (const float*)d_in[2];  // [1536, 768]
    const float* b1      = (const float*)d_in[3];  // [768]
    const float* W2      = (const float*)d_in[4];  // [768, 1]
    const float* b2      = (const float*)d_in[5];  // [1]
    const float* prior   = (const float*)d_in[6];  // [4096, 64]
    const float* nota    = (const float*)d_in[7];  // []
    const int*   midx    = (const int*)d_in[8];    // [T]
    const int*   cidx    = (const int*)d_in[9];    // [T]
    float* out = (float*)d_out;                    // [4096, 65]

    const int N = in_sizes[0] / HID;   // 4096
    const int T = in_sizes[1] / HID;   // 131072

    cudaFuncSetAttribute(gemm_kernel<false>, cudaFuncAttributeMaxDynamicSharedMemorySize, SMEM_BYTES);
    cudaFuncSetAttribute(gemm_kernel<true>,  cudaFuncAttributeMaxDynamicSharedMemorySize, SMEM_BYTES);

    // 0) out = 0.5*prior (+ nota col)
    init_out_kernel<<<(N * (MAXK + 1) + 255) / 256, 256>>>(out, prior, nota, N);

    // 1) W1T (fp16) = W1^T
    transpose_kernel<<<dim3(HID / 32, W1ROWS / 32), dim3(32, 8)>>>(W1);

    // 2) Mpart = mention @ W1_top + b1
    gemm_kernel<false><<<dim3(HID / BN, N / BM), NTHREADS, SMEM_BYTES>>>(
        mention, 0, b1, W2, b2, nullptr, nullptr, out);

    // 3) fused: cand @ W1_bot -> +Mpart -> relu -> @W2 (+b2) -> scatter-add
    gemm_kernel<true><<<dim3(HID / BN, T / BM), NTHREADS, SMEM_BYTES>>>(
        cand, HID, b1, W2, b2, midx, cidx, out);
}